// round 15
// baseline (speedup 1.0000x reference)
#include <cuda_runtime.h>
#include <cuda_fp16.h>

#define TSEQ    1024
#define NB      512
#define RMAX    7
#define NDIRBLK 74
#define NBLK    (2 * NDIRBLK)
#define VOCABP1 50001
#define LOG2E   1.4426950408889634f
#define HSTR    72    // hs16 row stride (halves), padded vs 64

// Precomputed zx table, COLUMN-PERMUTED: original gate-column j = g*64+u is
// stored at position p = (u>>2)*16 + g*4 + (u&3). Warp w of lstm_kernel needs
// exactly positions [16w, 16w+16) of each token row -> 64B contiguous.
__device__ float g_zw[2][VOCABP1][256];
// final hidden states: [dir][batch][64]
__device__ float g_h[2 * NB * 64];

static __device__ __forceinline__ unsigned long long pk2(float lo, float hi) {
    unsigned long long r;
    asm("mov.b64 %0, {%1,%2};" : "=l"(r) : "f"(lo), "f"(hi));
    return r;
}
static __device__ __forceinline__ void upk2(unsigned long long v, float &lo, float &hi) {
    asm("mov.b64 {%0,%1}, %2;" : "=f"(lo), "=f"(hi) : "l"(v));
}
static __device__ __forceinline__ void ffma2(unsigned long long &d,
                                             unsigned long long a,
                                             unsigned long long b) {
    asm("fma.rn.f32x2 %0, %1, %2, %0;" : "+l"(d) : "l"(a), "l"(b));
}
static __device__ __forceinline__ float tanha(float x) {
    float r; asm("tanh.approx.f32 %0, %1;" : "=f"(r) : "f"(x)); return r;
}
static __device__ __forceinline__ float sigm_t(float x) {
    return fmaf(0.5f, tanha(0.5f * x), 0.5f);
}
static __device__ __forceinline__ void hmma16816(float* d,
                                                 unsigned a0, unsigned a1,
                                                 unsigned a2, unsigned a3,
                                                 unsigned b0, unsigned b1) {
    asm volatile(
        "mma.sync.aligned.m16n8k16.row.col.f32.f16.f16.f32 "
        "{%0,%1,%2,%3}, {%4,%5,%6,%7}, {%8,%9}, {%0,%1,%2,%3};\n"
        : "+f"(d[0]), "+f"(d[1]), "+f"(d[2]), "+f"(d[3])
        : "r"(a0), "r"(a1), "r"(a2), "r"(a3), "r"(b0), "r"(b1));
}
static __device__ __forceinline__ unsigned smem_u32(const void* p) {
    unsigned a;
    asm("{ .reg .u64 t; cvta.to.shared.u64 t, %1; cvt.u32.u64 %0, t; }"
        : "=r"(a) : "l"(p));
    return a;
}
static __device__ __forceinline__ void cp_async16(unsigned dst, const void* src) {
    asm volatile("cp.async.ca.shared.global [%0], [%1], 16;" :: "r"(dst), "l"(src));
}
#define CP_COMMIT() asm volatile("cp.async.commit_group;" ::: "memory")
#define CP_WAIT2()  asm volatile("cp.async.wait_group 2;"  ::: "memory")

// ============================================================================
// Phase 1: zw table, permuted columns. Thread j owns OUTPUT position j and
// computes original gate-column jo(j) = ((j>>2)&3)*64 + (j>>4)*4 + (j&3)
// -> stores stay fully coalesced.
// ============================================================================
extern "C" __global__ void __launch_bounds__(256, 2)
zw_kernel(const float* __restrict__ emb,
          const float* __restrict__ Wf, const float* __restrict__ bf,
          const float* __restrict__ Wb, const float* __restrict__ bb)
{
    __shared__ __align__(16) float ebuf[64][64];
    const int dir  = blockIdx.y;
    const int base = blockIdx.x * 64;
    const int j    = threadIdx.x;
    const int jo   = ((j >> 2) & 3) * 64 + (j >> 4) * 4 + (j & 3);
    const float* W  = dir ? Wb : Wf;
    const float* bv = dir ? bb : bf;

    unsigned long long wreg[32];
#pragma unroll
    for (int p = 0; p < 32; p++)
        wreg[p] = pk2(W[(2 * p) * 256 + jo], W[(2 * p + 1) * 256 + jo]);
    const float bj = bv[jo];

#pragma unroll
    for (int i = 0; i < 16; i++) {
        const int lin = i * 256 + j;
        const int r = lin >> 6, c = lin & 63;
        const int row = base + r;
        ebuf[r][c] = (row < VOCABP1) ? emb[(long long)row * 64 + c] : 0.f;
    }
    __syncthreads();

    float* outp = &g_zw[dir][0][0];
#pragma unroll 1
    for (int r = 0; r < 64; r++) {
        if (base + r >= VOCABP1) break;
        const ulonglong2* srow = (const ulonglong2*)(&ebuf[r][0]);
        unsigned long long a0 = 0ull, a1 = 0ull;
#pragma unroll
        for (int q = 0; q < 8; q++) {
            const ulonglong2 v0 = srow[2 * q];
            const ulonglong2 v1 = srow[2 * q + 1];
            ffma2(a0, v0.x, wreg[4 * q + 0]);
            ffma2(a1, v0.y, wreg[4 * q + 1]);
            ffma2(a0, v1.x, wreg[4 * q + 2]);
            ffma2(a1, v1.y, wreg[4 * q + 3]);
        }
        float p0, p1, q0, q1;
        upk2(a0, p0, p1);
        upk2(a1, q0, q1);
        outp[(long long)(base + r) * 256 + j] = bj + ((p0 + q0) + (p1 + q1));
    }
}

// ============================================================================
// Phase 2: recurrent h@U via transposed tensor-core MMA, ONE barrier/step.
// zx path: per-warp cp.async of the warp's contiguous 64B slice of each of
// the 8 token rows into a PRIVATE triple-buffered smem region (depth-2:
// issue for t+2, wait_group 2, read buffer t%3). No cross-warp sync needed
// for zx. Consumer LDS (stride-20 rows) is bank-conflict-free.
// Fragment locality: c0/c1 <-> local col lq, c2/c3 <-> lq+8 (by construction
// of the g_zw permutation).
// ============================================================================
extern "C" __global__ void __launch_bounds__(512, 1)
lstm_kernel(const void* __restrict__ xraw,
            const float* __restrict__ Uf, const float* __restrict__ Ub)
{
    __shared__ __align__(16) __half hs16[2][8][HSTR];   // fp16 hidden, double buf
    __shared__ int idxs[8][8];                          // token ids, 8-slot ring
    __shared__ __align__(16) float zxs[3][16][8][20];   // zx bufs, 20-f row pad

    const int tid  = threadIdx.x;
    const int wid  = tid >> 5;
    const int lane = tid & 31;
    const int lq   = lane >> 2;        // 0..7
    const int lr   = lane & 3;         // 0..3
    const int g0   = lq >> 2;          // 0..1 : my "gate parity"

    const int dir   = (blockIdx.x >= NDIRBLK) ? 1 : 0;
    const int bslot = blockIdx.x - dir * NDIRBLK;
    const int base  = bslot * RMAX;
    const int nrows = min(RMAX, NB - base);

    const int uw     = wid * 4;
    const int myunit = uw + (lq & 3);
    const int myrow  = 2 * lr + g0;          // stage C row (0..7)
    const int colA   = myunit + 64 * g0;     // ORIGINAL U column for c0/c1

    const int*       x32 = (const int*)xraw;
    const long long* x64 = (const long long*)xraw;
    const bool is64 = ((x32[1] | x32[3] | x32[5] | x32[7]) == 0);

    const float* U   = dir ? Ub : Uf;
    const float* zwd = &g_zw[dir][0][0];

    // ---- A fragments: U^T fp16, permanent in registers (original cols) ----
    unsigned afr[4][4];
#pragma unroll
    for (int kt = 0; kt < 4; kt++) {
#pragma unroll
        for (int hh = 0; hh < 2; hh++) {
            const int k0 = kt * 16 + 2 * lr + 8 * hh;
            __half2 lo = __floats2half2_rn(U[k0 * 256 + colA],
                                           U[(k0 + 1) * 256 + colA]);
            __half2 hi = __floats2half2_rn(U[k0 * 256 + colA + 128],
                                           U[(k0 + 1) * 256 + colA + 128]);
            afr[kt][2 * hh]     = *(unsigned*)&lo;
            afr[kt][2 * hh + 1] = *(unsigned*)&hi;
        }
    }

    // ---- prologue: token ids (dead rows: zero all 8 slots), zero hs ----
    if (tid < 8) {
        if (tid < nrows) {
            const long long xb = (long long)(base + tid) * TSEQ;
#pragma unroll
            for (int q = 0; q < 4; q++) {
                const int tq = dir ? (TSEQ - 1 - q) : q;
                idxs[q][tid] = is64 ? (int)x64[xb + tq] : x32[xb + tq];
            }
        } else {
#pragma unroll
            for (int q = 0; q < 8; q++) idxs[q][tid] = 0;
        }
    }
    {
        unsigned* hz = (unsigned*)&hs16[0][0][0];
        const int nw = (2 * 8 * HSTR * 2) / 4;
        for (int i = tid; i < nw; i += 512) hz[i] = 0u;
    }
    __syncthreads();

    // per-warp cp.async addressing
    const unsigned zsm   = smem_u32(&zxs[0][0][0][0]);
    const unsigned zdst0 = zsm + wid * 640 + lq * 80 + lr * 16;  // + buf*10240
    const float*   zsrc0 = zwd + (wid << 4) + (lr << 2);         // + tok*256

    // prologue zx: buffers 0 (step 0) and 1 (step 1)
    {
        const long long t0 = idxs[0][lq];
        cp_async16(zdst0,         zsrc0 + t0 * 256);
        CP_COMMIT();
        const long long t1 = idxs[1][lq];
        cp_async16(zdst0 + 10240, zsrc0 + t1 * 256);
        CP_COMMIT();
    }

    float hreg = 0.f, creg = 0.f;
    int rb = 0;                         // current read buffer = t % 3

#pragma unroll 1
    for (int t = 0; t < TSEQ; t++) {
        const int p = t & 1;
        const int m = idxs[t & 7][myrow];

        // issue zx prefetch for t+2 into buffer (t+2)%3; ALWAYS commit
        const int pb = (rb >= 1) ? (rb - 1) : 2;   // (rb+2)%3
        if (t + 2 < TSEQ) {
            const long long tok = idxs[(t + 2) & 7][lq];
            cp_async16(zdst0 + pb * 10240, zsrc0 + tok * 256);
        }
        CP_COMMIT();

        // token id for t+4 into ring slot (t+4)&7
        if ((tid < nrows) && (t + 4 < TSEQ)) {
            const int tn = dir ? (TSEQ - 1 - (t + 4)) : (t + 4);
            const long long xb = (long long)(base + tid) * TSEQ;
            idxs[(t + 4) & 7][tid] = is64 ? (int)x64[xb + tn] : x32[xb + tn];
        }

        // wait for the group issued at t-2 (buffer rb) to complete
        CP_WAIT2();

        // zx accumulator inits (conflict-free LDS, stride-20 rows)
        const float* zrow = &zxs[rb][wid][0][0];
        const float zc0 = zrow[(2 * lr) * 20 + lq];
        const float zc1 = zrow[(2 * lr + 1) * 20 + lq];
        const float zc2 = zrow[(2 * lr) * 20 + lq + 8];
        const float zc3 = zrow[(2 * lr + 1) * 20 + lq + 8];

        // ========== stage B: z^T = U^T @ h^T + zx (4 HMMA, 2+2 split) ======
        unsigned bf[4][2];
#pragma unroll
        for (int kt = 0; kt < 4; kt++) {
            bf[kt][0] = *(const unsigned*)&hs16[p][lq][kt * 16 + 2 * lr];
            bf[kt][1] = *(const unsigned*)&hs16[p][lq][kt * 16 + 2 * lr + 8];
        }
        float dA[4] = {zc0, zc1, zc2, zc3};
        float dB[4] = {0.f, 0.f, 0.f, 0.f};
        hmma16816(dA, afr[0][0], afr[0][1], afr[0][2], afr[0][3], bf[0][0], bf[0][1]);
        hmma16816(dB, afr[2][0], afr[2][1], afr[2][2], afr[2][3], bf[2][0], bf[2][1]);
        hmma16816(dA, afr[1][0], afr[1][1], afr[1][2], afr[1][3], bf[1][0], bf[1][1]);
        hmma16816(dB, afr[3][0], afr[3][1], afr[3][2], afr[3][3], bf[3][0], bf[3][1]);
        float d[4];
#pragma unroll
        for (int i = 0; i < 4; i++) d[i] = dA[i] + dB[i];

        // ========== gate exchange: 2 shfl.xor(16) ==========
        const float sendA = g0 ? d[0] : d[1];
        const float sendB = g0 ? d[2] : d[3];
        const float recvA = __shfl_xor_sync(0xffffffffu, sendA, 16);
        const float recvB = __shfl_xor_sync(0xffffffffu, sendB, 16);
        const float zown0 = g0 ? d[1] : d[0];
        const float zown2 = g0 ? d[3] : d[2];
        const float zi = g0 ? recvA : zown0;
        const float zf = g0 ? zown0 : recvA;
        const float zg = g0 ? recvB : zown2;
        const float zo = g0 ? zown2 : recvB;

        // ========== stage C: gates + state update ==========
        {
            const float ig = sigm_t(zi);
            const float fg = sigm_t(zf);
            const float gg = tanha(zg);
            const float og = sigm_t(zo);
            const float cn = fmaf(fg, creg, ig * gg);
            const float hn = og * tanha(cn);
            if (m != 0) { creg = cn; hreg = hn; }
            hs16[p ^ 1][myrow][myunit] = __float2half(hreg);
        }

        rb = (rb >= 2) ? 0 : (rb + 1);
        __syncthreads();
    }

    if (myrow < nrows)
        g_h[(dir * NB + (base + myrow)) * 64 + myunit] = hreg;
}

// ============================================================================
// Head: out[b] = relu(concat(hf,hb) @ W1 + b1) @ W2 + b2
// ============================================================================
extern "C" __global__ void head_kernel(const float* __restrict__ W1,
                                       const float* __restrict__ b1,
                                       const float* __restrict__ W2,
                                       const float* __restrict__ b2,
                                       float* __restrict__ out)
{
    const int b = blockIdx.x;
    const int u = threadIdx.x;
    const float* hf = &g_h[b * 64];
    const float* hb = &g_h[(NB + b) * 64];
    float acc = b1[u];
#pragma unroll
    for (int k = 0; k < 64; k++) acc = fmaf(hf[k], W1[k * 32 + u], acc);
#pragma unroll
    for (int k = 0; k < 64; k++) acc = fmaf(hb[k], W1[(64 + k) * 32 + u], acc);
    float v = fmaxf(acc, 0.f) * W2[u];
#pragma unroll
    for (int off = 16; off > 0; off >>= 1)
        v += __shfl_xor_sync(0xffffffffu, v, off);
    if (u == 0) out[b] = v + b2[0];
}

extern "C" void kernel_launch(void* const* d_in, const int* in_sizes, int n_in,
                              void* d_out, int out_size)
{
    const void*  x   = d_in[0];
    const float* emb = (const float*)d_in[1];
    const float* Wf  = (const float*)d_in[2];
    const float* Uf  = (const float*)d_in[3];
    const float* bf  = (const float*)d_in[4];
    const float* Wb  = (const float*)d_in[5];
    const float* Ub  = (const float*)d_in[6];
    const float* bb  = (const float*)d_in[7];
    const float* W1  = (const float*)d_in[8];
    const float* b1  = (const float*)d_in[9];
    const float* W2  = (const float*)d_in[10];
    const float* b2  = (const float*)d_in[11];

    zw_kernel<<<dim3((VOCABP1 + 63) / 64, 2), 256>>>(emb, Wf, bf, Wb, bb);
    lstm_kernel<<<NBLK, 512>>>(x, Uf, Ub);
    head_kernel<<<NB, 32>>>(W1, b1, W2, b2, (float*)d_out);
}

// round 16
// speedup vs baseline: 1.7342x; 1.7342x over previous
#include <cuda_runtime.h>
#include <cuda_fp16.h>

#define TSEQ    1024
#define NB      512
#define RMAX    7
#define NDIRBLK 74
#define NBLK    (2 * NDIRBLK)
#define VOCABP1 50001
#define LOG2E   1.4426950408889634f
#define HSTR    72    // hs16 row stride (halves), padded vs 64

// Precomputed zx table, fp16, COLUMN-PERMUTED (51 MB -> L2-resident):
// original gate-column g*64+u stored at p = 16*(u>>2) + 2*(4*(g&1)+(u&3)) + (g>>1).
// Lane (wid, lq, lr) of lstm_kernel reads halves [16*wid + 2*lq, +1] = its
// (gate g0, gate g0+2) pair -> one 4B LDG.32 per sequence row.
__device__ __half g_zw[2][VOCABP1][256];
// final hidden states: [dir][batch][64]
__device__ float g_h[2 * NB * 64];

static __device__ __forceinline__ unsigned long long pk2(float lo, float hi) {
    unsigned long long r;
    asm("mov.b64 %0, {%1,%2};" : "=l"(r) : "f"(lo), "f"(hi));
    return r;
}
static __device__ __forceinline__ void upk2(unsigned long long v, float &lo, float &hi) {
    asm("mov.b64 {%0,%1}, %2;" : "=f"(lo), "=f"(hi) : "l"(v));
}
static __device__ __forceinline__ void ffma2(unsigned long long &d,
                                             unsigned long long a,
                                             unsigned long long b) {
    asm("fma.rn.f32x2 %0, %1, %2, %0;" : "+l"(d) : "l"(a), "l"(b));
}
static __device__ __forceinline__ float tanha(float x) {
    float r; asm("tanh.approx.f32 %0, %1;" : "=f"(r) : "f"(x)); return r;
}
static __device__ __forceinline__ float sigm_t(float x) {
    return fmaf(0.5f, tanha(0.5f * x), 0.5f);
}
static __device__ __forceinline__ void hmma16816(float* d,
                                                 unsigned a0, unsigned a1,
                                                 unsigned a2, unsigned a3,
                                                 unsigned b0, unsigned b1) {
    asm volatile(
        "mma.sync.aligned.m16n8k16.row.col.f32.f16.f16.f32 "
        "{%0,%1,%2,%3}, {%4,%5,%6,%7}, {%8,%9}, {%0,%1,%2,%3};\n"
        : "+f"(d[0]), "+f"(d[1]), "+f"(d[2]), "+f"(d[3])
        : "r"(a0), "r"(a1), "r"(a2), "r"(a3), "r"(b0), "r"(b1));
}

// ============================================================================
// Phase 1: zw table, fp16 permuted. Thread j computes ORIGINAL column j
// (fully coalesced weight loads), stages the permuted half at sbuf[r][p(j)]
// (conflict-free STS.16), then the block copies sbuf -> g_zw coalesced.
// ============================================================================
extern "C" __global__ void __launch_bounds__(256, 2)
zw_kernel(const float* __restrict__ emb,
          const float* __restrict__ Wf, const float* __restrict__ bf,
          const float* __restrict__ Wb, const float* __restrict__ bb)
{
    __shared__ __align__(16) float  ebuf[64][64];
    __shared__ __align__(16) __half sbuf[64][256];
    const int dir  = blockIdx.y;
    const int base = blockIdx.x * 64;
    const int j    = threadIdx.x;
    const int g    = j >> 6, u = j & 63;
    const int pj   = ((u >> 2) << 4) + (((g & 1) * 4 + (u & 3)) << 1) + (g >> 1);
    const float* W  = dir ? Wb : Wf;
    const float* bv = dir ? bb : bf;

    unsigned long long wreg[32];
#pragma unroll
    for (int p = 0; p < 32; p++)
        wreg[p] = pk2(W[(2 * p) * 256 + j], W[(2 * p + 1) * 256 + j]);
    const float bj = bv[j];

#pragma unroll
    for (int i = 0; i < 16; i++) {
        const int lin = i * 256 + j;
        const int r = lin >> 6, c = lin & 63;
        const int row = base + r;
        ebuf[r][c] = (row < VOCABP1) ? emb[(long long)row * 64 + c] : 0.f;
    }
    __syncthreads();

    const int nr = min(64, VOCABP1 - base);
#pragma unroll 1
    for (int r = 0; r < 64; r++) {
        if (r >= nr) break;
        const ulonglong2* srow = (const ulonglong2*)(&ebuf[r][0]);
        unsigned long long a0 = 0ull, a1 = 0ull;
#pragma unroll
        for (int q = 0; q < 8; q++) {
            const ulonglong2 v0 = srow[2 * q];
            const ulonglong2 v1 = srow[2 * q + 1];
            ffma2(a0, v0.x, wreg[4 * q + 0]);
            ffma2(a1, v0.y, wreg[4 * q + 1]);
            ffma2(a0, v1.x, wreg[4 * q + 2]);
            ffma2(a1, v1.y, wreg[4 * q + 3]);
        }
        float p0, p1, q0, q1;
        upk2(a0, p0, p1);
        upk2(a1, q0, q1);
        sbuf[r][pj] = __float2half_rn(bj + ((p0 + q0) + (p1 + q1)));
    }
    __syncthreads();

    // coalesced copy: nr rows x 512B
    uint4* dst = (uint4*)&g_zw[dir][base][0];
    const uint4* src = (const uint4*)&sbuf[0][0];
    for (int i = j; i < nr * 32; i += 256) dst[i] = src[i];
}

// ============================================================================
// Phase 2: recurrent h@U via transposed tensor-core MMA (R12 skeleton).
// 148 blocks x 512 threads, ONE barrier/step, depth-2 zx prefetch.
// zx now fp16-permuted: 2 LDG.32 per warp per step (16 sector-accesses,
// half of R12), converted with 2 half2->float2 at consume time.
// ============================================================================
extern "C" __global__ void __launch_bounds__(512, 1)
lstm_kernel(const void* __restrict__ xraw,
            const float* __restrict__ Uf, const float* __restrict__ Ub)
{
    __shared__ __align__(16) __half hs16[2][8][HSTR];  // fp16 hidden, double buf
    __shared__ int idxs[8][8];                         // token ids, 8-slot ring

    const int tid  = threadIdx.x;
    const int wid  = tid >> 5;
    const int lane = tid & 31;
    const int lq   = lane >> 2;        // 0..7
    const int lr   = lane & 3;         // 0..3
    const int g0   = lq >> 2;          // 0..1 : my "gate parity"

    const int dir   = (blockIdx.x >= NDIRBLK) ? 1 : 0;
    const int bslot = blockIdx.x - dir * NDIRBLK;
    const int base  = bslot * RMAX;
    const int nrows = min(RMAX, NB - base);

    const int uw     = wid * 4;
    const int myunit = uw + (lq & 3);
    const int myrow  = 2 * lr + g0;          // stage C row (0..7)
    const int colA   = myunit + 64 * g0;     // ORIGINAL U column for c0/c1

    const int*       x32 = (const int*)xraw;
    const long long* x64 = (const long long*)xraw;
    const bool is64 = ((x32[1] | x32[3] | x32[5] | x32[7]) == 0);

    const float*  U   = dir ? Ub : Uf;
    const __half* zwd = &g_zw[dir][0][0];
    const int     zoff = (wid << 4) + (lq << 1);   // halves into a token row

    // ---- A fragments: U^T fp16, permanent in registers (original cols) ----
    unsigned afr[4][4];
#pragma unroll
    for (int kt = 0; kt < 4; kt++) {
#pragma unroll
        for (int hh = 0; hh < 2; hh++) {
            const int k0 = kt * 16 + 2 * lr + 8 * hh;
            __half2 lo = __floats2half2_rn(U[k0 * 256 + colA],
                                           U[(k0 + 1) * 256 + colA]);
            __half2 hi = __floats2half2_rn(U[k0 * 256 + colA + 128],
                                           U[(k0 + 1) * 256 + colA + 128]);
            afr[kt][2 * hh]     = *(unsigned*)&lo;
            afr[kt][2 * hh + 1] = *(unsigned*)&hi;
        }
    }

    // ---- prologue: token ids (dead rows: zero ALL 8 slots), zero hs ----
    if (tid < 8) {
        if (tid < nrows) {
            const long long xb = (long long)(base + tid) * TSEQ;
#pragma unroll
            for (int q = 0; q < 4; q++) {
                const int tq = dir ? (TSEQ - 1 - q) : q;
                idxs[q][tid] = is64 ? (int)x64[xb + tq] : x32[xb + tq];
            }
        } else {
#pragma unroll
            for (int q = 0; q < 8; q++) idxs[q][tid] = 0;
        }
    }
    {
        unsigned* hz = (unsigned*)&hs16[0][0][0];
        const int nw = (2 * 8 * HSTR * 2) / 4;
        for (int i = tid; i < nw; i += 512) hz[i] = 0u;
    }
    __syncthreads();

    // zx ring (raw half2 words): zc = step t, zn = step t+1
    unsigned zcH01, zcH23, znH01, znH23;
    {
        const long long tA0 = idxs[0][2 * lr], tB0 = idxs[0][2 * lr + 1];
        zcH01 = *(const unsigned*)(zwd + tA0 * 256 + zoff);
        zcH23 = *(const unsigned*)(zwd + tB0 * 256 + zoff);
        const long long tA1 = idxs[1][2 * lr], tB1 = idxs[1][2 * lr + 1];
        znH01 = *(const unsigned*)(zwd + tA1 * 256 + zoff);
        znH23 = *(const unsigned*)(zwd + tB1 * 256 + zoff);
    }
    float hreg = 0.f, creg = 0.f;

#pragma unroll 1
    for (int t = 0; t < TSEQ; t++) {
        const int p = t & 1;
        const int m = idxs[t & 7][myrow];

        // zx prefetch for step t+2 (depth-2 slack)
        unsigned z2H01 = 0u, z2H23 = 0u;
        if (t + 2 < TSEQ) {
            const long long tA = idxs[(t + 2) & 7][2 * lr];
            const long long tB = idxs[(t + 2) & 7][2 * lr + 1];
            z2H01 = *(const unsigned*)(zwd + tA * 256 + zoff);
            z2H23 = *(const unsigned*)(zwd + tB * 256 + zoff);
        }
        // token id for step t+4 into ring slot (t+4)&7
        if ((tid < nrows) && (t + 4 < TSEQ)) {
            const int tn = dir ? (TSEQ - 1 - (t + 4)) : (t + 4);
            const long long xb = (long long)(base + tid) * TSEQ;
            idxs[(t + 4) & 7][tid] = is64 ? (int)x64[xb + tn] : x32[xb + tn];
        }

        // ========== stage B: z^T = U^T @ h^T + zx (4 HMMA, 2+2 split) ======
        unsigned bf[4][2];
#pragma unroll
        for (int kt = 0; kt < 4; kt++) {
            bf[kt][0] = *(const unsigned*)&hs16[p][lq][kt * 16 + 2 * lr];
            bf[kt][1] = *(const unsigned*)&hs16[p][lq][kt * 16 + 2 * lr + 8];
        }
        const float2 f01 = __half22float2(*(const __half2*)&zcH01); // (g0, g0+2) seq 2lr
        const float2 f23 = __half22float2(*(const __half2*)&zcH23); // (g0, g0+2) seq 2lr+1
        float dA[4] = {f01.x, f23.x, f01.y, f23.y};
        float dB[4] = {0.f, 0.f, 0.f, 0.f};
        hmma16816(dA, afr[0][0], afr[0][1], afr[0][2], afr[0][3], bf[0][0], bf[0][1]);
        hmma16816(dB, afr[2][0], afr[2][1], afr[2][2], afr[2][3], bf[2][0], bf[2][1]);
        hmma16816(dA, afr[1][0], afr[1][1], afr[1][2], afr[1][3], bf[1][0], bf[1][1]);
        hmma16816(dB, afr[3][0], afr[3][1], afr[3][2], afr[3][3], bf[3][0], bf[3][1]);
        float d[4];
#pragma unroll
        for (int i = 0; i < 4; i++) d[i] = dA[i] + dB[i];

        // ========== gate exchange: 2 shfl.xor(16) ==========
        const float sendA = g0 ? d[0] : d[1];
        const float sendB = g0 ? d[2] : d[3];
        const float recvA = __shfl_xor_sync(0xffffffffu, sendA, 16);
        const float recvB = __shfl_xor_sync(0xffffffffu, sendB, 16);
        const float zown0 = g0 ? d[1] : d[0];
        const float zown2 = g0 ? d[3] : d[2];
        const float zi = g0 ? recvA : zown0;
        const float zf = g0 ? zown0 : recvA;
        const float zg = g0 ? recvB : zown2;
        const float zo = g0 ? zown2 : recvB;

        // ========== stage C: gates + state update ==========
        {
            const float ig = sigm_t(zi);
            const float fg = sigm_t(zf);
            const float gg = tanha(zg);
            const float og = sigm_t(zo);
            const float cn = fmaf(fg, creg, ig * gg);
            const float hn = og * tanha(cn);
            if (m != 0) { creg = cn; hreg = hn; }
            hs16[p ^ 1][myrow][myunit] = __float2half(hreg);
        }

        // rotate the zx ring
        zcH01 = znH01; zcH23 = znH23;
        znH01 = z2H01; znH23 = z2H23;
        __syncthreads();
    }

    if (myrow < nrows)
        g_h[(dir * NB + (base + myrow)) * 64 + myunit] = hreg;
}

// ============================================================================
// Head: out[b] = relu(concat(hf,hb) @ W1 + b1) @ W2 + b2
// ============================================================================
extern "C" __global__ void head_kernel(const float* __restrict__ W1,
                                       const float* __restrict__ b1,
                                       const float* __restrict__ W2,
                                       const float* __restrict__ b2,
                                       float* __restrict__ out)
{
    const int b = blockIdx.x;
    const int u = threadIdx.x;
    const float* hf = &g_h[b * 64];
    const float* hb = &g_h[(NB + b) * 64];
    float acc = b1[u];
#pragma unroll
    for (int k = 0; k < 64; k++) acc = fmaf(hf[k], W1[k * 32 + u], acc);
#pragma unroll
    for (int k = 0; k < 64; k++) acc = fmaf(hb[k], W1[(64 + k) * 32 + u], acc);
    float v = fmaxf(acc, 0.f) * W2[u];
#pragma unroll
    for (int off = 16; off > 0; off >>= 1)
        v += __shfl_xor_sync(0xffffffffu, v, off);
    if (u == 0) out[b] = v + b2[0];
}

extern "C" void kernel_launch(void* const* d_in, const int* in_sizes, int n_in,
                              void* d_out, int out_size)
{
    const void*  x   = d_in[0];
    const float* emb = (const float*)d_in[1];
    const float* Wf  = (const float*)d_in[2];
    const float* Uf  = (const float*)d_in[3];
    const float* bf  = (const float*)d_in[4];
    const float* Wb  = (const float*)d_in[5];
    const float* Ub  = (const float*)d_in[6];
    const float* bb  = (const float*)d_in[7];
    const float* W1  = (const float*)d_in[8];
    const float* b1  = (const float*)d_in[9];
    const float* W2  = (const float*)d_in[10];
    const float* b2  = (const float*)d_in[11];

    zw_kernel<<<dim3((VOCABP1 + 63) / 64, 2), 256>>>(emb, Wf, bf, Wb, bb);
    lstm_kernel<<<NBLK, 512>>>(x, Uf, Ub);
    head_kernel<<<NB, 32>>>(W1, b1, W2, b2, (float*)d_out);
}

// round 17
// speedup vs baseline: 1.7536x; 1.0112x over previous
#include <cuda_runtime.h>
#include <cuda_fp16.h>

#define TSEQ    1024
#define NB      512
#define NDIRBLK 148
#define NBLK    (2 * NDIRBLK)
#define VOCABP1 50001
#define LOG2E   1.4426950408889634f
#define HSTR    72    // hs16 row stride (halves), padded vs 64

// Precomputed zx table, fp16, COLUMN-PERMUTED (51 MB -> L2-resident):
// original gate-column g*64+u stored at p = 16*(u>>2) + 2*(4*(g&1)+(u&3)) + (g>>1).
__device__ __half g_zw[2][VOCABP1][256];
// final hidden states: [dir][batch][64]
__device__ float g_h[2 * NB * 64];

static __device__ __forceinline__ unsigned long long pk2(float lo, float hi) {
    unsigned long long r;
    asm("mov.b64 %0, {%1,%2};" : "=l"(r) : "f"(lo), "f"(hi));
    return r;
}
static __device__ __forceinline__ void upk2(unsigned long long v, float &lo, float &hi) {
    asm("mov.b64 {%0,%1}, %2;" : "=f"(lo), "=f"(hi) : "l"(v));
}
static __device__ __forceinline__ void ffma2(unsigned long long &d,
                                             unsigned long long a,
                                             unsigned long long b) {
    asm("fma.rn.f32x2 %0, %1, %2, %0;" : "+l"(d) : "l"(a), "l"(b));
}
static __device__ __forceinline__ float tanha(float x) {
    float r; asm("tanh.approx.f32 %0, %1;" : "=f"(r) : "f"(x)); return r;
}
static __device__ __forceinline__ float sigm_t(float x) {
    return fmaf(0.5f, tanha(0.5f * x), 0.5f);
}
static __device__ __forceinline__ void hmma16816(float* d,
                                                 unsigned a0, unsigned a1,
                                                 unsigned a2, unsigned a3,
                                                 unsigned b0, unsigned b1) {
    asm volatile(
        "mma.sync.aligned.m16n8k16.row.col.f32.f16.f16.f32 "
        "{%0,%1,%2,%3}, {%4,%5,%6,%7}, {%8,%9}, {%0,%1,%2,%3};\n"
        : "+f"(d[0]), "+f"(d[1]), "+f"(d[2]), "+f"(d[3])
        : "r"(a0), "r"(a1), "r"(a2), "r"(a3), "r"(b0), "r"(b1));
}

// ============================================================================
// Phase 1: zw table, fp16 permuted (proven R16 version).
// ============================================================================
extern "C" __global__ void __launch_bounds__(256, 2)
zw_kernel(const float* __restrict__ emb,
          const float* __restrict__ Wf, const float* __restrict__ bf,
          const float* __restrict__ Wb, const float* __restrict__ bb)
{
    __shared__ __align__(16) float  ebuf[64][64];
    __shared__ __align__(16) __half sbuf[64][256];
    const int dir  = blockIdx.y;
    const int base = blockIdx.x * 64;
    const int j    = threadIdx.x;
    const int g    = j >> 6, u = j & 63;
    const int pj   = ((u >> 2) << 4) + (((g & 1) * 4 + (u & 3)) << 1) + (g >> 1);
    const float* W  = dir ? Wb : Wf;
    const float* bv = dir ? bb : bf;

    unsigned long long wreg[32];
#pragma unroll
    for (int p = 0; p < 32; p++)
        wreg[p] = pk2(W[(2 * p) * 256 + j], W[(2 * p + 1) * 256 + j]);
    const float bj = bv[j];

#pragma unroll
    for (int i = 0; i < 16; i++) {
        const int lin = i * 256 + j;
        const int r = lin >> 6, c = lin & 63;
        const int row = base + r;
        ebuf[r][c] = (row < VOCABP1) ? emb[(long long)row * 64 + c] : 0.f;
    }
    __syncthreads();

    const int nr = min(64, VOCABP1 - base);
#pragma unroll 1
    for (int r = 0; r < 64; r++) {
        if (r >= nr) break;
        const ulonglong2* srow = (const ulonglong2*)(&ebuf[r][0]);
        unsigned long long a0 = 0ull, a1 = 0ull;
#pragma unroll
        for (int q = 0; q < 8; q++) {
            const ulonglong2 v0 = srow[2 * q];
            const ulonglong2 v1 = srow[2 * q + 1];
            ffma2(a0, v0.x, wreg[4 * q + 0]);
            ffma2(a1, v0.y, wreg[4 * q + 1]);
            ffma2(a0, v1.x, wreg[4 * q + 2]);
            ffma2(a1, v1.y, wreg[4 * q + 3]);
        }
        float p0, p1, q0, q1;
        upk2(a0, p0, p1);
        upk2(a1, q0, q1);
        sbuf[r][pj] = __float2half_rn(bj + ((p0 + q0) + (p1 + q1)));
    }
    __syncthreads();

    uint4* dst = (uint4*)&g_zw[dir][base][0];
    const uint4* src = (const uint4*)&sbuf[0][0];
    for (int i = j; i < nr * 32; i += 256) dst[i] = src[i];
}

// ============================================================================
// Phase 2: recurrent LSTM, 2 CTAs/SM. 296 blocks x 256 threads (8 warps).
// Per block: 3-4 sequences placed at EVEN MMA N-slots (seq s <-> row 2s).
// Warp w owns 32 z-cols as two M=16 tiles (units 8w+4m+cu, gates g0/g0+2);
// 8 HMMA/warp/step. Lane's stage-C task: tile = its gate parity g0 ->
// (seq lr, unit 8w+4*g0+cu); one shfl.xor(16) pair-swap delivers the other
// two gates -> exactly 1 task / 5 MUFU per lane (MUFU parity with R16).
// Two co-resident blocks have independent barriers -> the serial per-step
// chain of one block hides under the other's issue.
// ============================================================================
extern "C" __global__ void __launch_bounds__(256, 2)
lstm_kernel(const void* __restrict__ xraw,
            const float* __restrict__ Uf, const float* __restrict__ Ub)
{
    __shared__ __align__(16) __half hs16[2][8][HSTR];  // fp16 hidden, double buf
    __shared__ int idxs[8][4];                         // token ids, 8-slot ring

    const int tid  = threadIdx.x;
    const int wid  = tid >> 5;         // 0..7
    const int lane = tid & 31;
    const int lq   = lane >> 2;        // 0..7
    const int lr   = lane & 3;         // 0..3 : sequence index
    const int g0   = lq >> 2;          // 0..1 : gate parity
    const int cu   = lq & 3;           // unit within tile

    const int dir   = (blockIdx.x >= NDIRBLK) ? 1 : 0;
    const int bslot = blockIdx.x - dir * NDIRBLK;
    // 512 sequences over 148 blocks: 68 blocks of 4, 80 blocks of 3
    const int base  = (bslot < 68) ? bslot * 4 : 272 + (bslot - 68) * 3;
    const int nrows = (bslot < 68) ? 4 : 3;

    const int myunit = 8 * wid + 4 * g0 + cu;   // stage C unit

    const int*       x32 = (const int*)xraw;
    const long long* x64 = (const long long*)xraw;
    const bool is64 = ((x32[1] | x32[3] | x32[5] | x32[7]) == 0);

    const float*  U   = dir ? Ub : Uf;
    const __half* zwd = &g_zw[dir][0][0];
    // half-offsets into a permuted token row, one per tile
    const int zoff0 = 16 * (2 * wid + 0) + 2 * (4 * g0 + cu);
    const int zoff1 = 16 * (2 * wid + 1) + 2 * (4 * g0 + cu);

    // ---- A fragments: U^T fp16, 2 tiles, permanent in registers ----
    unsigned afr[2][4][4];
#pragma unroll
    for (int mt = 0; mt < 2; mt++) {
        const int colA = (8 * wid + 4 * mt + cu) + 64 * g0;
#pragma unroll
        for (int kt = 0; kt < 4; kt++) {
#pragma unroll
            for (int hh = 0; hh < 2; hh++) {
                const int k0 = kt * 16 + 2 * lr + 8 * hh;
                __half2 lo = __floats2half2_rn(U[k0 * 256 + colA],
                                               U[(k0 + 1) * 256 + colA]);
                __half2 hi = __floats2half2_rn(U[k0 * 256 + colA + 128],
                                               U[(k0 + 1) * 256 + colA + 128]);
                afr[mt][kt][2 * hh]     = *(unsigned*)&lo;
                afr[mt][kt][2 * hh + 1] = *(unsigned*)&hi;
            }
        }
    }

    // ---- prologue: token ids (dead seqs: zero ALL 8 slots), zero hs ----
    if (tid < 4) {
        if (tid < nrows) {
            const long long xb = (long long)(base + tid) * TSEQ;
#pragma unroll
            for (int q = 0; q < 4; q++) {
                const int tq = dir ? (TSEQ - 1 - q) : q;
                idxs[q][tid] = is64 ? (int)x64[xb + tq] : x32[xb + tq];
            }
        } else {
#pragma unroll
            for (int q = 0; q < 8; q++) idxs[q][tid] = 0;
        }
    }
    {
        unsigned* hz = (unsigned*)&hs16[0][0][0];
        const int nw = (2 * 8 * HSTR * 2) / 4;   // 576 words
        for (int i = tid; i < nw; i += 256) hz[i] = 0u;
    }
    __syncthreads();

    // zx ring (raw half2 words, [tile]): zc = step t, zn = t+1
    unsigned zc0, zc1, zn0, zn1;
    {
        const long long t0 = idxs[0][lr];
        zc0 = *(const unsigned*)(zwd + t0 * 256 + zoff0);
        zc1 = *(const unsigned*)(zwd + t0 * 256 + zoff1);
        const long long t1 = idxs[1][lr];
        zn0 = *(const unsigned*)(zwd + t1 * 256 + zoff0);
        zn1 = *(const unsigned*)(zwd + t1 * 256 + zoff1);
    }
    float hreg = 0.f, creg = 0.f;

#pragma unroll 1
    for (int t = 0; t < TSEQ; t++) {
        const int p = t & 1;
        const int m = idxs[t & 7][lr];          // my sequence's mask token

        // zx prefetch for step t+2 (depth-2 slack)
        unsigned z20 = 0u, z21 = 0u;
        if (t + 2 < TSEQ) {
            const long long tok = idxs[(t + 2) & 7][lr];
            z20 = *(const unsigned*)(zwd + tok * 256 + zoff0);
            z21 = *(const unsigned*)(zwd + tok * 256 + zoff1);
        }
        // token id for step t+4 into ring slot (t+4)&7
        if ((tid < nrows) && (t + 4 < TSEQ)) {
            const int tn = dir ? (TSEQ - 1 - (t + 4)) : (t + 4);
            const long long xb = (long long)(base + tid) * TSEQ;
            idxs[(t + 4) & 7][tid] = is64 ? (int)x64[xb + tn] : x32[xb + tn];
        }

        // ========== stage B: two M=16 tiles, 8 HMMA (2+2 split each) =======
        unsigned bf[4][2];
#pragma unroll
        for (int kt = 0; kt < 4; kt++) {
            bf[kt][0] = *(const unsigned*)&hs16[p][lq][kt * 16 + 2 * lr];
            bf[kt][1] = *(const unsigned*)&hs16[p][lq][kt * 16 + 2 * lr + 8];
        }
        const float2 f0 = __half22float2(*(const __half2*)&zc0); // tile0 (g0, g0+2)
        const float2 f1 = __half22float2(*(const __half2*)&zc1); // tile1
        float d0A[4] = {f0.x, 0.f, f0.y, 0.f};
        float d0B[4] = {0.f, 0.f, 0.f, 0.f};
        float d1A[4] = {f1.x, 0.f, f1.y, 0.f};
        float d1B[4] = {0.f, 0.f, 0.f, 0.f};
        hmma16816(d0A, afr[0][0][0], afr[0][0][1], afr[0][0][2], afr[0][0][3], bf[0][0], bf[0][1]);
        hmma16816(d0B, afr[0][2][0], afr[0][2][1], afr[0][2][2], afr[0][2][3], bf[2][0], bf[2][1]);
        hmma16816(d1A, afr[1][0][0], afr[1][0][1], afr[1][0][2], afr[1][0][3], bf[0][0], bf[0][1]);
        hmma16816(d1B, afr[1][2][0], afr[1][2][1], afr[1][2][2], afr[1][2][3], bf[2][0], bf[2][1]);
        hmma16816(d0A, afr[0][1][0], afr[0][1][1], afr[0][1][2], afr[0][1][3], bf[1][0], bf[1][1]);
        hmma16816(d0B, afr[0][3][0], afr[0][3][1], afr[0][3][2], afr[0][3][3], bf[3][0], bf[3][1]);
        hmma16816(d1A, afr[1][1][0], afr[1][1][1], afr[1][1][2], afr[1][1][3], bf[1][0], bf[1][1]);
        hmma16816(d1B, afr[1][3][0], afr[1][3][1], afr[1][3][2], afr[1][3][3], bf[3][0], bf[3][1]);
        // valid outputs: index 0 (col lq, seq lr) and index 2 (col lq+8, seq lr)
        const float t0g0 = d0A[0] + d0B[0];   // tile0, gate g0
        const float t0g2 = d0A[2] + d0B[2];   // tile0, gate g0+2
        const float t1g0 = d1A[0] + d1B[0];   // tile1, gate g0
        const float t1g2 = d1A[2] + d1B[2];   // tile1, gate g0+2

        // ========== gate exchange: my task tile = g0; partner = lane^16 ====
        // send my values of tile (1-g0); receive partner's of tile g0.
        const float sendA = g0 ? t0g0 : t1g0;
        const float sendB = g0 ? t0g2 : t1g2;
        const float recvA = __shfl_xor_sync(0xffffffffu, sendA, 16);
        const float recvB = __shfl_xor_sync(0xffffffffu, sendB, 16);
        const float ownA  = g0 ? t1g0 : t0g0;   // my tile, gate g0
        const float ownB  = g0 ? t1g2 : t0g2;   // my tile, gate g0+2
        const float zi = g0 ? recvA : ownA;     // gate 0
        const float zf = g0 ? ownA : recvA;     // gate 1
        const float zg = g0 ? recvB : ownB;     // gate 2
        const float zo = g0 ? ownB : recvB;     // gate 3

        // ========== stage C: one task per lane ==========
        {
            const float ig = sigm_t(zi);
            const float fg = sigm_t(zf);
            const float gg = tanha(zg);
            const float og = sigm_t(zo);
            const float cn = fmaf(fg, creg, ig * gg);
            const float hn = og * tanha(cn);
            if (m != 0) { creg = cn; hreg = hn; }
            hs16[p ^ 1][2 * lr][myunit] = __float2half(hreg);
        }

        // rotate the zx ring
        zc0 = zn0; zc1 = zn1;
        zn0 = z20; zn1 = z21;
        __syncthreads();
    }

    if (lr < nrows)
        g_h[(dir * NB + (base + lr)) * 64 + myunit] = hreg;
}

// ============================================================================
// Head: out[b] = relu(concat(hf,hb) @ W1 + b1) @ W2 + b2
// ============================================================================
extern "C" __global__ void head_kernel(const float* __restrict__ W1,
                                       const float* __restrict__ b1,
                                       const float* __restrict__ W2,
                                       const float* __restrict__ b2,
                                       float* __restrict__ out)
{
    const int b = blockIdx.x;
    const int u = threadIdx.x;
    const float* hf = &g_h[b * 64];
    const float* hb = &g_h[(NB + b) * 64];
    float acc = b1[u];
#pragma unroll
    for (int k = 0; k < 64; k++) acc = fmaf(hf[k], W1[k * 32 + u], acc);
#pragma unroll
    for (int k = 0; k < 64; k++) acc = fmaf(hb[k], W1[(64 + k) * 32 + u], acc);
    float v = fmaxf(acc, 0.f) * W2[u];
#pragma unroll
    for (int off = 16; off > 0; off >>= 1)
        v += __shfl_xor_sync(0xffffffffu, v, off);
    if (u == 0) out[b] = v + b2[0];
}

extern "C" void kernel_launch(void* const* d_in, const int* in_sizes, int n_in,
                              void* d_out, int out_size)
{
    const void*  x   = d_in[0];
    const float* emb = (const float*)d_in[1];
    const float* Wf  = (const float*)d_in[2];
    const float* Uf  = (const float*)d_in[3];
    const float* bf  = (const float*)d_in[4];
    const float* Wb  = (const float*)d_in[5];
    const float* Ub  = (const float*)d_in[6];
    const float* bb  = (const float*)d_in[7];
    const float* W1  = (const float*)d_in[8];
    const float* b1  = (const float*)d_in[9];
    const float* W2  = (const float*)d_in[10];
    const float* b2  = (const float*)d_in[11];

    zw_kernel<<<dim3((VOCABP1 + 63) / 64, 2), 256>>>(emb, Wf, bf, Wb, bb);
    lstm_kernel<<<NBLK, 256>>>(x, Uf, Ub);
    head_kernel<<<NB, 32>>>(W1, b1, W2, b2, (float*)d_out);
}